// round 12
// baseline (speedup 1.0000x reference)
#include <cuda_runtime.h>
#include <cuda_bf16.h>
#include <cstdint>

// Problem constants (fixed by dataset): b=4, n=4096 -> M=16384 tokens, d=256, h=8
#define D    256
#define H    8
#define HD   2048
#define MAXM 16384

// Scratch (device globals: allocation-free rule)
__device__ float g_qkv[(size_t)MAXM * 3 * HD];   // per token: [q(2048) | k(2048) | v(2048)]
__device__ float g_o1 [(size_t)MAXM * HD];       // attention output before Wo

// ---------------------------------------------------------------------------
// bf16-split GEMM:  C = A(MxK_f32) @ B(KxN_f32) + bias, computed as a single
// bf16 tensor-core GEMM over K' = 3K:
//   A' = [hi(A) | lo(A) | hi(A)],  B' = [hi(B); hi(B); lo(B)]
// => A'B' = Ahi*Bhi + Alo*Bhi + Ahi*Blo   (drops only lo*lo ~ 2^-16 rel)
// Conversion happens on the fly while staging tiles into shared memory.
// Software pipeline: global loads for tile kb+1 prefetched into registers
// during compute of tile kb; smem is DOUBLE-BUFFERED so only ONE
// __syncthreads() per k-block is needed.
//
// Tile: 128x128 CTA, BK'=32. 256 threads = 8 warps in 4(M) x 2(N);
// each warp computes 32x64 via 2x8 mma.m16n8k16 tiles.
// grid.z selects among up to 3 (B, bias, C-offset) triples -> fused QKV.
// ---------------------------------------------------------------------------
#define GBM 128
#define GBN 128
#define GBK 32
#define LDSA 40   // halves per A-smem row (padding: conflict-free frag loads)
#define LDSB 40   // halves per B-smem row (B stored transposed: [n][k])

__device__ __forceinline__ __nv_bfloat16 bf_hi(float x) {
    return __float2bfloat16_rn(x);
}
__device__ __forceinline__ __nv_bfloat16 bf_lo(float x) {
    float h = __bfloat162float(__float2bfloat16_rn(x));
    return __float2bfloat16_rn(x - h);
}

__device__ __forceinline__ void mma16816(float c[4], const uint32_t a[4],
                                         uint32_t b0, uint32_t b1) {
    asm volatile(
        "mma.sync.aligned.m16n8k16.row.col.f32.bf16.bf16.f32 "
        "{%0,%1,%2,%3}, {%4,%5,%6,%7}, {%8,%9}, {%0,%1,%2,%3};\n"
        : "+f"(c[0]), "+f"(c[1]), "+f"(c[2]), "+f"(c[3])
        : "r"(a[0]), "r"(a[1]), "r"(a[2]), "r"(a[3]), "r"(b0), "r"(b1));
}

__global__ void __launch_bounds__(256)
gemm_bf16x3(const float* __restrict__ A,
            const float* __restrict__ B0, const float* __restrict__ bias0,
            const float* __restrict__ B1, const float* __restrict__ bias1,
            const float* __restrict__ B2, const float* __restrict__ bias2,
            float* __restrict__ C, int c_zstride,
            int K, int lda, int ldb, int ldc)
{
    __shared__ __nv_bfloat16 As[2][GBM * LDSA];   // [buf][row][k]
    __shared__ __nv_bfloat16 Bs[2][GBN * LDSB];   // [buf][n][k] (transposed)

    const int t    = threadIdx.x;
    const int lane = t & 31;
    const int w    = t >> 5;
    const int wm   = w & 3;    // warp M index: offset wm*32
    const int wn   = w >> 2;   // warp N index: offset wn*64
    const int g    = lane >> 2;      // groupID 0..7
    const int tg   = lane & 3;       // threadID_in_group 0..3

    const int z = blockIdx.z;
    const float* B    = (z == 0) ? B0    : (z == 1) ? B1    : B2;
    const float* bias = (z == 0) ? bias0 : (z == 1) ? bias1 : bias2;
    float* Cz = C + (size_t)z * c_zstride;

    const float* Ag = A + (size_t)blockIdx.y * GBM * lda;
    const float* Bg = B + (size_t)blockIdx.x * GBN;

    // Per-thread load coordinates (4 vectors each for A and B)
    //   A tile: 128 rows x 32 k  -> lin = t + i*256; r = lin>>3; c4 = lin&7
    //   B tile: 32 k x 128 n     -> lin = t + i*256; kr = lin>>5; n4 = lin&31
    float4 pa[4], pb[4];

    float acc[2][8][4];
#pragma unroll
    for (int mt = 0; mt < 2; mt++)
#pragma unroll
        for (int nt = 0; nt < 8; nt++)
#pragma unroll
            for (int i = 0; i < 4; i++) acc[mt][nt][i] = 0.0f;

    const int nblocks = (3 * K) / GBK;

    // ---- prologue: load tile 0 into regs, stage to smem buf 0 ----
    {
#pragma unroll
        for (int i = 0; i < 4; i++) {
            const int lin = t + i * 256;
            pa[i] = *(const float4*)(Ag + (size_t)(lin >> 3) * lda + (lin & 7) * 4);
            pb[i] = *(const float4*)(Bg + (size_t)(lin >> 5) * ldb + (lin & 31) * 4);
        }
#pragma unroll
        for (int i = 0; i < 4; i++) {
            const int lin = t + i * 256;
            __nv_bfloat16* p = &As[0][(lin >> 3) * LDSA + (lin & 7) * 4];
            p[0] = bf_hi(pa[i].x); p[1] = bf_hi(pa[i].y);
            p[2] = bf_hi(pa[i].z); p[3] = bf_hi(pa[i].w);
            const int kr = lin >> 5, n4 = lin & 31;
            Bs[0][(n4 * 4 + 0) * LDSB + kr] = bf_hi(pb[i].x);
            Bs[0][(n4 * 4 + 1) * LDSB + kr] = bf_hi(pb[i].y);
            Bs[0][(n4 * 4 + 2) * LDSB + kr] = bf_hi(pb[i].z);
            Bs[0][(n4 * 4 + 3) * LDSB + kr] = bf_hi(pb[i].w);
        }
    }
    __syncthreads();

    for (int kb = 0; kb < nblocks; kb++) {
        const int cur = kb & 1;
        const int nxt = cur ^ 1;
        const int kb1 = kb + 1;

        // ---- prefetch tile kb+1 globals into registers ----
        if (kb1 < nblocks) {
            const int kstart1 = kb1 * GBK;
            const int part1   = kstart1 / K;
            const int bk1     = kstart1 - part1 * K;
#pragma unroll
            for (int i = 0; i < 4; i++) {
                const int lin = t + i * 256;
                pa[i] = *(const float4*)(Ag + (size_t)(lin >> 3) * lda + bk1 + (lin & 7) * 4);
                pb[i] = *(const float4*)(Bg + (size_t)(bk1 + (lin >> 5)) * ldb + (lin & 31) * 4);
            }
        }

        // ---- compute on tile kb from buf `cur` (2 k-steps of 16) ----
#pragma unroll
        for (int ks = 0; ks < 2; ks++) {
            const int kw = ks * 8 + tg;          // 32-bit word index into a row

            uint32_t af[2][4];
#pragma unroll
            for (int mt = 0; mt < 2; mt++) {
                const int rb = wm * 32 + mt * 16 + g;
                const uint32_t* pr  = (const uint32_t*)&As[cur][rb * LDSA];
                const uint32_t* pr8 = (const uint32_t*)&As[cur][(rb + 8) * LDSA];
                af[mt][0] = pr [kw];       // (row,   k)
                af[mt][1] = pr8[kw];       // (row+8, k)
                af[mt][2] = pr [kw + 4];   // (row,   k+8)
                af[mt][3] = pr8[kw + 4];   // (row+8, k+8)
            }
#pragma unroll
            for (int nt = 0; nt < 8; nt++) {
                const int cb = wn * 64 + nt * 8 + g;
                const uint32_t* pc = (const uint32_t*)&Bs[cur][cb * LDSB];
                const uint32_t b0 = pc[kw];        // (k,   n)
                const uint32_t b1 = pc[kw + 4];    // (k+8, n)
#pragma unroll
                for (int mt = 0; mt < 2; mt++)
                    mma16816(acc[mt][nt], af[mt], b0, b1);
            }
        }

        // ---- convert + store tile kb+1 into buf `nxt`, then ONE barrier ----
        if (kb1 < nblocks) {
            const int kstart1 = kb1 * GBK;
            const int part1   = kstart1 / K;
            const bool aLo    = (part1 == 1);     // A': hi | lo | hi
            const bool bLo    = (part1 == 2);     // B': hi ; hi ; lo
#pragma unroll
            for (int i = 0; i < 4; i++) {
                const int lin = t + i * 256;
                __nv_bfloat16* p = &As[nxt][(lin >> 3) * LDSA + (lin & 7) * 4];
                if (aLo) {
                    p[0] = bf_lo(pa[i].x); p[1] = bf_lo(pa[i].y);
                    p[2] = bf_lo(pa[i].z); p[3] = bf_lo(pa[i].w);
                } else {
                    p[0] = bf_hi(pa[i].x); p[1] = bf_hi(pa[i].y);
                    p[2] = bf_hi(pa[i].z); p[3] = bf_hi(pa[i].w);
                }
                const int kr = lin >> 5, n4 = lin & 31;
                __nv_bfloat16 h0, h1, h2, h3;
                if (bLo) {
                    h0 = bf_lo(pb[i].x); h1 = bf_lo(pb[i].y);
                    h2 = bf_lo(pb[i].z); h3 = bf_lo(pb[i].w);
                } else {
                    h0 = bf_hi(pb[i].x); h1 = bf_hi(pb[i].y);
                    h2 = bf_hi(pb[i].z); h3 = bf_hi(pb[i].w);
                }
                Bs[nxt][(n4 * 4 + 0) * LDSB + kr] = h0;
                Bs[nxt][(n4 * 4 + 1) * LDSB + kr] = h1;
                Bs[nxt][(n4 * 4 + 2) * LDSB + kr] = h2;
                Bs[nxt][(n4 * 4 + 3) * LDSB + kr] = h3;
            }
            __syncthreads();   // tile kb+1 visible; also fences buf reuse
        }
    }

    // ---- epilogue: + bias, float2 stores ----
    const int row_base = blockIdx.y * GBM + wm * 32 + g;
    const int col_base = blockIdx.x * GBN + wn * 64 + tg * 2;
#pragma unroll
    for (int nt = 0; nt < 8; nt++) {
        const int col = col_base + nt * 8;
        const float b0 = bias[col], b1 = bias[col + 1];
#pragma unroll
        for (int mt = 0; mt < 2; mt++) {
            const int r = row_base + mt * 16;
            float2 v0 = make_float2(acc[mt][nt][0] + b0, acc[mt][nt][1] + b1);
            float2 v1 = make_float2(acc[mt][nt][2] + b0, acc[mt][nt][3] + b1);
            *(float2*)(Cz + (size_t)r * ldc + col)       = v0;
            *(float2*)(Cz + (size_t)(r + 8) * ldc + col) = v1;
        }
    }
}

// ---------------------------------------------------------------------------
// Per-token head-vs-head attention (fp32 path).
// One CTA per token (256 threads, 8 warps); warp w owns head w.
// ---------------------------------------------------------------------------
__global__ void __launch_bounds__(256)
attn_kernel(const float* __restrict__ qkv, float* __restrict__ o1)
{
    __shared__ float s[3 * HD];
    const size_t tok = blockIdx.x;

    const float4* src = (const float4*)(qkv + tok * (size_t)(3 * HD));
    float4* dst = (float4*)s;
#pragma unroll
    for (int i = threadIdx.x; i < (3 * HD) / 4; i += 256) dst[i] = src[i];
    __syncthreads();

    const float* sq = s;
    const float* sk = s + HD;
    const float* sv = s + 2 * HD;

    const int w    = threadIdx.x >> 5;
    const int lane = threadIdx.x & 31;
    const float scale = 0.0625f;   // 1/sqrt(256)

    float a[H];
#pragma unroll
    for (int gg = 0; gg < H; gg++) {
        float sum = 0.0f;
#pragma unroll
        for (int m = 0; m < 8; m++) {
            const int dd = lane + 32 * m;
            sum += sq[w * D + dd] * sk[gg * D + dd];
        }
#pragma unroll
        for (int off = 16; off; off >>= 1)
            sum += __shfl_xor_sync(0xffffffffu, sum, off);
        a[gg] = sum * scale;
    }

    float mx = a[0];
#pragma unroll
    for (int gg = 1; gg < H; gg++) mx = fmaxf(mx, a[gg]);
    float ssum = 0.0f;
#pragma unroll
    for (int gg = 0; gg < H; gg++) { a[gg] = expf(a[gg] - mx); ssum += a[gg]; }
    const float inv = 1.0f / ssum;
#pragma unroll
    for (int gg = 0; gg < H; gg++) a[gg] *= inv;

    float* orow = o1 + tok * (size_t)HD + w * D;
#pragma unroll
    for (int m = 0; m < 8; m++) {
        const int dd = lane + 32 * m;
        float o = 0.0f;
#pragma unroll
        for (int gg = 0; gg < H; gg++) o += a[gg] * sv[gg * D + dd];
        orow[dd] = o;
    }
}

// ---------------------------------------------------------------------------
extern "C" void kernel_launch(void* const* d_in, const int* in_sizes, int n_in,
                              void* d_out, int out_size)
{
    const float* x  = (const float*)d_in[0];
    const float* Wq = (const float*)d_in[1];
    const float* bq = (const float*)d_in[2];
    const float* Wk = (const float*)d_in[3];
    const float* bk = (const float*)d_in[4];
    const float* Wv = (const float*)d_in[5];
    const float* bv = (const float*)d_in[6];
    const float* Wo = (const float*)d_in[7];
    const float* bo = (const float*)d_in[8];
    float* out = (float*)d_out;

    const int M = in_sizes[0] / D;   // 16384 tokens

    float *qkv, *o1;
    cudaGetSymbolAddress((void**)&qkv, g_qkv);
    cudaGetSymbolAddress((void**)&o1,  g_o1);

    dim3 blk(256);

    // Fused QKV projections: X(M x 256) @ {Wq,Wk,Wv}(256 x 2048) + b
    // grid.z picks the weight set; C offset = z*HD within the 3*HD row.
    dim3 gA(HD / GBN, M / GBM, 3);
    gemm_bf16x3<<<gA, blk>>>(x, Wq, bq, Wk, bk, Wv, bv,
                             qkv, HD, D, D, HD, 3 * HD);

    // Per-token attention
    attn_kernel<<<M, blk>>>(qkv, o1);

    // Output projection: O1(M x 2048) @ Wo(2048 x 256) + bo
    dim3 gC(D / GBN, M / GBM, 1);
    gemm_bf16x3<<<gC, blk>>>(o1, Wo, bo, Wo, bo, Wo, bo,
                             out, 0, HD, HD, D, D);
}

// round 13
// speedup vs baseline: 2.6461x; 2.6461x over previous
#include <cuda_runtime.h>
#include <cuda_bf16.h>
#include <cstdint>

// Problem constants (fixed by dataset): b=4, n=4096 -> M=16384 tokens, d=256, h=8
#define D    256
#define H    8
#define HD   2048
#define MAXM 16384

// Scratch (device globals: allocation-free rule)
__device__ float g_qkv[(size_t)MAXM * 3 * HD];   // per token: [q(2048) | k(2048) | v(2048)]
__device__ float g_o1 [(size_t)MAXM * HD];       // attention output before Wo

// ---------------------------------------------------------------------------
// bf16-split GEMM:  C = A(MxK_f32) @ B(KxN_f32) + bias  over K' = 3K:
//   A' = [hi(A) | lo(A) | hi(A)],  B' = [hi(B); hi(B); lo(B)]
// R12 profile: L1/shared pipe 76% (LSU-bound), tensor 13%. This version cuts
// LSU ops ~4x: ldmatrix.x4 fragment loads (A direct, B transposed) and
// vectorized uint2 staging stores into a [k][n] B layout.
// Double-buffered smem, register prefetch pipeline, 1 barrier/iter.
// Tile: 128x128 CTA, BK'=32, 256 threads = 8 warps (4M x 2N), warp = 32x64.
// ---------------------------------------------------------------------------
#define GBM 128
#define GBN 128
#define GBK 32
#define LDSA  40    // halves per A-smem row (stride 20 words: ldmatrix conflict-free)
#define LDSBN 136   // halves per B-smem row [k][n] (stride 68 words: conflict-free)

__device__ __forceinline__ uint32_t pack_hi(float x, float y) {
    __nv_bfloat162 v = __float22bfloat162_rn(make_float2(x, y));
    return *(uint32_t*)&v;
}
__device__ __forceinline__ uint32_t pack_lo(float x, float y) {
    float hx = __bfloat162float(__float2bfloat16_rn(x));
    float hy = __bfloat162float(__float2bfloat16_rn(y));
    __nv_bfloat162 v = __float22bfloat162_rn(make_float2(x - hx, y - hy));
    return *(uint32_t*)&v;
}

__device__ __forceinline__ void mma16816(float c[4], const uint32_t a[4],
                                         uint32_t b0, uint32_t b1) {
    asm volatile(
        "mma.sync.aligned.m16n8k16.row.col.f32.bf16.bf16.f32 "
        "{%0,%1,%2,%3}, {%4,%5,%6,%7}, {%8,%9}, {%0,%1,%2,%3};\n"
        : "+f"(c[0]), "+f"(c[1]), "+f"(c[2]), "+f"(c[3])
        : "r"(a[0]), "r"(a[1]), "r"(a[2]), "r"(a[3]), "r"(b0), "r"(b1));
}

__device__ __forceinline__ void ldsm_x4(uint32_t r[4], uint32_t addr) {
    asm volatile("ldmatrix.sync.aligned.m8n8.x4.shared.b16 {%0,%1,%2,%3}, [%4];"
                 : "=r"(r[0]), "=r"(r[1]), "=r"(r[2]), "=r"(r[3]) : "r"(addr));
}
__device__ __forceinline__ void ldsm_x4_t(uint32_t r[4], uint32_t addr) {
    asm volatile("ldmatrix.sync.aligned.m8n8.x4.trans.shared.b16 {%0,%1,%2,%3}, [%4];"
                 : "=r"(r[0]), "=r"(r[1]), "=r"(r[2]), "=r"(r[3]) : "r"(addr));
}

__global__ void __launch_bounds__(256)
gemm_bf16x3(const float* __restrict__ A,
            const float* __restrict__ B0, const float* __restrict__ bias0,
            const float* __restrict__ B1, const float* __restrict__ bias1,
            const float* __restrict__ B2, const float* __restrict__ bias2,
            float* __restrict__ C, int c_zstride,
            int K, int lda, int ldb, int ldc)
{
    __shared__ __nv_bfloat16 As[2][GBM * LDSA];    // [buf][row][k]
    __shared__ __nv_bfloat16 Bs[2][GBK * LDSBN];   // [buf][k][n]

    const int t    = threadIdx.x;
    const int lane = t & 31;
    const int w    = t >> 5;
    const int wm   = w & 3;          // warp M index: offset wm*32
    const int wn   = w >> 2;         // warp N index: offset wn*64
    const int g    = lane >> 2;      // groupID 0..7
    const int tg   = lane & 3;       // threadID_in_group 0..3
    // ldmatrix lane->address constants (same pattern for A and B):
    const int l7   = lane & 7;
    const int sub  = lane >> 3;
    const int mrow = (sub & 1) * 8 + l7;   // row-within-16 offset
    const int mcol = (sub >> 1) * 8;       // col-within-16 offset (halves)

    const int z = blockIdx.z;
    const float* B    = (z == 0) ? B0    : (z == 1) ? B1    : B2;
    const float* bias = (z == 0) ? bias0 : (z == 1) ? bias1 : bias2;
    float* Cz = C + (size_t)z * c_zstride;

    const float* Ag = A + (size_t)blockIdx.y * GBM * lda;
    const float* Bg = B + (size_t)blockIdx.x * GBN;

    // Per-thread load coords: A tile 128r x 32k: lin -> (lin>>3, lin&7 float4)
    //                         B tile 32k x 128n: lin -> (lin>>5, lin&31 float4)
    float4 pa[4], pb[4];

    float acc[2][8][4];
#pragma unroll
    for (int mt = 0; mt < 2; mt++)
#pragma unroll
        for (int nt = 0; nt < 8; nt++)
#pragma unroll
            for (int i = 0; i < 4; i++) acc[mt][nt][i] = 0.0f;

    const int nblocks = (3 * K) / GBK;

    // ---- prologue: load tile 0, stage (hi/hi) into buf 0 ----
    {
#pragma unroll
        for (int i = 0; i < 4; i++) {
            const int lin = t + i * 256;
            pa[i] = *(const float4*)(Ag + (size_t)(lin >> 3) * lda + (lin & 7) * 4);
            pb[i] = *(const float4*)(Bg + (size_t)(lin >> 5) * ldb + (lin & 31) * 4);
        }
#pragma unroll
        for (int i = 0; i < 4; i++) {
            const int lin = t + i * 256;
            uint2 va, vb;
            va.x = pack_hi(pa[i].x, pa[i].y);  va.y = pack_hi(pa[i].z, pa[i].w);
            vb.x = pack_hi(pb[i].x, pb[i].y);  vb.y = pack_hi(pb[i].z, pb[i].w);
            *(uint2*)&As[0][(lin >> 3) * LDSA + (lin & 7) * 4]   = va;
            *(uint2*)&Bs[0][(lin >> 5) * LDSBN + (lin & 31) * 4] = vb;
        }
    }
    __syncthreads();

    for (int kb = 0; kb < nblocks; kb++) {
        const int cur = kb & 1;
        const int nxt = cur ^ 1;
        const int kb1 = kb + 1;

        // ---- prefetch tile kb+1 globals into registers ----
        if (kb1 < nblocks) {
            const int kstart1 = kb1 * GBK;
            const int part1   = kstart1 / K;
            const int bk1     = kstart1 - part1 * K;
#pragma unroll
            for (int i = 0; i < 4; i++) {
                const int lin = t + i * 256;
                pa[i] = *(const float4*)(Ag + (size_t)(lin >> 3) * lda + bk1 + (lin & 7) * 4);
                pb[i] = *(const float4*)(Bg + (size_t)(bk1 + (lin >> 5)) * ldb + (lin & 31) * 4);
            }
        }

        // ---- compute on tile kb from buf `cur` (2 k-steps of 16) ----
#pragma unroll
        for (int ks = 0; ks < 2; ks++) {
            uint32_t a[2][4];
#pragma unroll
            for (int mt = 0; mt < 2; mt++) {
                uint32_t addr = (uint32_t)__cvta_generic_to_shared(
                    &As[cur][(wm * 32 + mt * 16 + mrow) * LDSA + ks * 16 + mcol]);
                ldsm_x4(a[mt], addr);
            }
#pragma unroll
            for (int ntp = 0; ntp < 4; ntp++) {
                uint32_t b[4];
                uint32_t addr = (uint32_t)__cvta_generic_to_shared(
                    &Bs[cur][(ks * 16 + mrow) * LDSBN + wn * 64 + ntp * 16 + mcol]);
                ldsm_x4_t(b, addr);
                // b[0],b[1] = (b0,b1) for n-block ntp*2; b[2],b[3] for ntp*2+1
                mma16816(acc[0][ntp * 2 + 0], a[0], b[0], b[1]);
                mma16816(acc[1][ntp * 2 + 0], a[1], b[0], b[1]);
                mma16816(acc[0][ntp * 2 + 1], a[0], b[2], b[3]);
                mma16816(acc[1][ntp * 2 + 1], a[1], b[2], b[3]);
            }
        }

        // ---- convert + store tile kb+1 into buf `nxt`, then ONE barrier ----
        if (kb1 < nblocks) {
            const int kstart1 = kb1 * GBK;
            const int part1   = kstart1 / K;
            const bool aLo    = (part1 == 1);     // A': hi | lo | hi
            const bool bLo    = (part1 == 2);     // B': hi ; hi ; lo
#pragma unroll
            for (int i = 0; i < 4; i++) {
                const int lin = t + i * 256;
                uint2 va, vb;
                if (aLo) { va.x = pack_lo(pa[i].x, pa[i].y); va.y = pack_lo(pa[i].z, pa[i].w); }
                else     { va.x = pack_hi(pa[i].x, pa[i].y); va.y = pack_hi(pa[i].z, pa[i].w); }
                if (bLo) { vb.x = pack_lo(pb[i].x, pb[i].y); vb.y = pack_lo(pb[i].z, pb[i].w); }
                else     { vb.x = pack_hi(pb[i].x, pb[i].y); vb.y = pack_hi(pb[i].z, pb[i].w); }
                *(uint2*)&As[nxt][(lin >> 3) * LDSA + (lin & 7) * 4]   = va;
                *(uint2*)&Bs[nxt][(lin >> 5) * LDSBN + (lin & 31) * 4] = vb;
            }
            __syncthreads();   // tile kb+1 visible; also fences buf reuse
        }
    }

    // ---- epilogue: + bias, float2 stores ----
    const int row_base = blockIdx.y * GBM + wm * 32 + g;
    const int col_base = blockIdx.x * GBN + wn * 64 + tg * 2;
#pragma unroll
    for (int nt = 0; nt < 8; nt++) {
        const int col = col_base + nt * 8;
        const float b0 = bias[col], b1 = bias[col + 1];
#pragma unroll
        for (int mt = 0; mt < 2; mt++) {
            const int r = row_base + mt * 16;
            float2 v0 = make_float2(acc[mt][nt][0] + b0, acc[mt][nt][1] + b1);
            float2 v1 = make_float2(acc[mt][nt][2] + b0, acc[mt][nt][3] + b1);
            *(float2*)(Cz + (size_t)r * ldc + col)       = v0;
            *(float2*)(Cz + (size_t)(r + 8) * ldc + col) = v1;
        }
    }
}

// ---------------------------------------------------------------------------
// Per-token head-vs-head attention (fp32 path).
// One CTA per token (256 threads, 8 warps); warp w owns head w.
// ---------------------------------------------------------------------------
__global__ void __launch_bounds__(256)
attn_kernel(const float* __restrict__ qkv, float* __restrict__ o1)
{
    __shared__ float s[3 * HD];
    const size_t tok = blockIdx.x;

    const float4* src = (const float4*)(qkv + tok * (size_t)(3 * HD));
    float4* dst = (float4*)s;
#pragma unroll
    for (int i = threadIdx.x; i < (3 * HD) / 4; i += 256) dst[i] = src[i];
    __syncthreads();

    const float* sq = s;
    const float* sk = s + HD;
    const float* sv = s + 2 * HD;

    const int w    = threadIdx.x >> 5;
    const int lane = threadIdx.x & 31;
    const float scale = 0.0625f;   // 1/sqrt(256)

    float a[H];
#pragma unroll
    for (int gg = 0; gg < H; gg++) {
        float sum = 0.0f;
#pragma unroll
        for (int m = 0; m < 8; m++) {
            const int dd = lane + 32 * m;
            sum += sq[w * D + dd] * sk[gg * D + dd];
        }
#pragma unroll
        for (int off = 16; off; off >>= 1)
            sum += __shfl_xor_sync(0xffffffffu, sum, off);
        a[gg] = sum * scale;
    }

    float mx = a[0];
#pragma unroll
    for (int gg = 1; gg < H; gg++) mx = fmaxf(mx, a[gg]);
    float ssum = 0.0f;
#pragma unroll
    for (int gg = 0; gg < H; gg++) { a[gg] = expf(a[gg] - mx); ssum += a[gg]; }
    const float inv = 1.0f / ssum;
#pragma unroll
    for (int gg = 0; gg < H; gg++) a[gg] *= inv;

    float* orow = o1 + tok * (size_t)HD + w * D;
#pragma unroll
    for (int m = 0; m < 8; m++) {
        const int dd = lane + 32 * m;
        float o = 0.0f;
#pragma unroll
        for (int gg = 0; gg < H; gg++) o += a[gg] * sv[gg * D + dd];
        orow[dd] = o;
    }
}

// ---------------------------------------------------------------------------
extern "C" void kernel_launch(void* const* d_in, const int* in_sizes, int n_in,
                              void* d_out, int out_size)
{
    const float* x  = (const float*)d_in[0];
    const float* Wq = (const float*)d_in[1];
    const float* bq = (const float*)d_in[2];
    const float* Wk = (const float*)d_in[3];
    const float* bk = (const float*)d_in[4];
    const float* Wv = (const float*)d_in[5];
    const float* bv = (const float*)d_in[6];
    const float* Wo = (const float*)d_in[7];
    const float* bo = (const float*)d_in[8];
    float* out = (float*)d_out;

    const int M = in_sizes[0] / D;   // 16384 tokens

    float *qkv, *o1;
    cudaGetSymbolAddress((void**)&qkv, g_qkv);
    cudaGetSymbolAddress((void**)&o1,  g_o1);

    dim3 blk(256);

    // Fused QKV projections: X(M x 256) @ {Wq,Wk,Wv}(256 x 2048) + b
    dim3 gA(HD / GBN, M / GBM, 3);
    gemm_bf16x3<<<gA, blk>>>(x, Wq, bq, Wk, bk, Wv, bv,
                             qkv, HD, D, D, HD, 3 * HD);

    // Per-token attention
    attn_kernel<<<M, blk>>>(qkv, o1);

    // Output projection: O1(M x 2048) @ Wo(2048 x 256) + bo
    dim3 gC(D / GBN, M / GBM, 1);
    gemm_bf16x3<<<gC, blk>>>(o1, Wo, bo, Wo, bo, Wo, bo,
                             out, 0, HD, HD, D, D);
}

// round 14
// speedup vs baseline: 3.7608x; 1.4213x over previous
#include <cuda_runtime.h>
#include <cuda_bf16.h>
#include <cstdint>

// Problem constants (fixed by dataset): b=4, n=4096 -> M=16384 tokens, d=256, h=8
#define D    256
#define H    8
#define HD   2048
#define MAXM 16384

// Scratch (device globals: allocation-free rule)
__device__ float g_qkv[(size_t)MAXM * 3 * HD];   // per token: [q(2048) | k(2048) | v(2048)]
__device__ float g_o1 [(size_t)MAXM * HD];       // attention output before Wo

// ---------------------------------------------------------------------------
// bf16-split GEMM, v3:  C = A @ B + bias with fp32 accuracy via
//   C ≈ Ahi·Bhi + Alo·Bhi + Ahi·Blo      (drops only lo·lo ~ 2^-16 rel)
// R13 profile: L1 pipe 70% because the K'=3K sweep re-reads globals ~3x.
// v3 loads each original k-block ONCE, converts hi+lo once, stages all four
// tiles (Ahi,Alo,Bhi,Blo), and runs the 3 MMA groups against the staged data
// (Ahi fragments reused across 2 groups). LDG 3x down, STS/ldmatrix 1.5x down.
// Double-buffered, register prefetch, 1 barrier per k-block.
// Tile: 128x128 CTA, k-block 16 (orig K), 8 warps (4M x 2N), warp = 32x64.
// ---------------------------------------------------------------------------
#define GBM 128
#define GBN 128
#define BKO 16     // original-K block per stage
#define LDSA2 24   // halves per A-smem row (stride 12 words: ldsm conflict-free)
#define LDSB2 136  // halves per B-smem row [k][n] (stride 68 words: conflict-free)

__device__ __forceinline__ void pack_hilo(float x, float y,
                                          uint32_t& hi, uint32_t& lo) {
    __nv_bfloat16 hx = __float2bfloat16_rn(x);
    __nv_bfloat16 hy = __float2bfloat16_rn(y);
    __nv_bfloat162 h2; h2.x = hx; h2.y = hy;
    hi = *(uint32_t*)&h2;
    __nv_bfloat162 l2 = __float22bfloat162_rn(
        make_float2(x - __bfloat162float(hx), y - __bfloat162float(hy)));
    lo = *(uint32_t*)&l2;
}

__device__ __forceinline__ void mma16816(float c[4], const uint32_t a[4],
                                         uint32_t b0, uint32_t b1) {
    asm volatile(
        "mma.sync.aligned.m16n8k16.row.col.f32.bf16.bf16.f32 "
        "{%0,%1,%2,%3}, {%4,%5,%6,%7}, {%8,%9}, {%0,%1,%2,%3};\n"
        : "+f"(c[0]), "+f"(c[1]), "+f"(c[2]), "+f"(c[3])
        : "r"(a[0]), "r"(a[1]), "r"(a[2]), "r"(a[3]), "r"(b0), "r"(b1));
}

__device__ __forceinline__ void ldsm_x4(uint32_t r[4], uint32_t addr) {
    asm volatile("ldmatrix.sync.aligned.m8n8.x4.shared.b16 {%0,%1,%2,%3}, [%4];"
                 : "=r"(r[0]), "=r"(r[1]), "=r"(r[2]), "=r"(r[3]) : "r"(addr));
}
__device__ __forceinline__ void ldsm_x4_t(uint32_t r[4], uint32_t addr) {
    asm volatile("ldmatrix.sync.aligned.m8n8.x4.trans.shared.b16 {%0,%1,%2,%3}, [%4];"
                 : "=r"(r[0]), "=r"(r[1]), "=r"(r[2]), "=r"(r[3]) : "r"(addr));
}

__global__ void __launch_bounds__(256)
gemm_bf16x3(const float* __restrict__ A,
            const float* __restrict__ B0, const float* __restrict__ bias0,
            const float* __restrict__ B1, const float* __restrict__ bias1,
            const float* __restrict__ B2, const float* __restrict__ bias2,
            float* __restrict__ C, int c_zstride,
            int K, int lda, int ldb, int ldc)
{
    __shared__ __nv_bfloat16 Ah[2][GBM * LDSA2];   // [buf][row][k]  hi(A)
    __shared__ __nv_bfloat16 Al[2][GBM * LDSA2];   // [buf][row][k]  lo(A)
    __shared__ __nv_bfloat16 Bh[2][BKO * LDSB2];   // [buf][k][n]    hi(B)
    __shared__ __nv_bfloat16 Bl[2][BKO * LDSB2];   // [buf][k][n]    lo(B)

    const int t    = threadIdx.x;
    const int lane = t & 31;
    const int w    = t >> 5;
    const int wm   = w & 3;          // warp M index: offset wm*32
    const int wn   = w >> 2;         // warp N index: offset wn*64
    const int g    = lane >> 2;      // groupID 0..7
    const int tg   = lane & 3;       // threadID_in_group 0..3
    // ldmatrix lane->address mapping
    const int l7   = lane & 7;
    const int sub  = lane >> 3;
    const int mrow = (sub & 1) * 8 + l7;   // row-within-16
    const int mcol = (sub >> 1) * 8;       // col-within-16 (halves)

    const int z = blockIdx.z;
    const float* B    = (z == 0) ? B0    : (z == 1) ? B1    : B2;
    const float* bias = (z == 0) ? bias0 : (z == 1) ? bias1 : bias2;
    float* Cz = C + (size_t)z * c_zstride;

    const float* Ag = A + (size_t)blockIdx.y * GBM * lda;
    const float* Bg = B + (size_t)blockIdx.x * GBN;

    // Per-thread staging coords (2 float4 each for A and B per k-block):
    //   A tile 128r x 16k: lin -> (lin>>2, lin&3)   [512 float4]
    //   B tile 16k x 128n: lin -> (lin>>5, lin&31)  [512 float4]
    float4 pa[2], pb[2];

    float acc[2][8][4];
#pragma unroll
    for (int mt = 0; mt < 2; mt++)
#pragma unroll
        for (int nt = 0; nt < 8; nt++)
#pragma unroll
            for (int i = 0; i < 4; i++) acc[mt][nt][i] = 0.0f;

    const int nblocks = K / BKO;

    // ---- stage helper done inline: pack hi+lo, store all four tiles ----
    // ---- prologue: load k-block 0, stage into buf 0 ----
    {
#pragma unroll
        for (int i = 0; i < 2; i++) {
            const int lin = t + i * 256;
            pa[i] = *(const float4*)(Ag + (size_t)(lin >> 2) * lda + (lin & 3) * 4);
            pb[i] = *(const float4*)(Bg + (size_t)(lin >> 5) * ldb + (lin & 31) * 4);
        }
#pragma unroll
        for (int i = 0; i < 2; i++) {
            const int lin = t + i * 256;
            uint2 vah, val, vbh, vbl;
            pack_hilo(pa[i].x, pa[i].y, vah.x, val.x);
            pack_hilo(pa[i].z, pa[i].w, vah.y, val.y);
            pack_hilo(pb[i].x, pb[i].y, vbh.x, vbl.x);
            pack_hilo(pb[i].z, pb[i].w, vbh.y, vbl.y);
            const int aoff = (lin >> 2) * LDSA2 + (lin & 3) * 4;
            const int boff = (lin >> 5) * LDSB2 + (lin & 31) * 4;
            *(uint2*)&Ah[0][aoff] = vah;  *(uint2*)&Al[0][aoff] = val;
            *(uint2*)&Bh[0][boff] = vbh;  *(uint2*)&Bl[0][boff] = vbl;
        }
    }
    __syncthreads();

    for (int kb = 0; kb < nblocks; kb++) {
        const int cur = kb & 1;
        const int nxt = cur ^ 1;
        const int kb1 = kb + 1;

        // ---- prefetch k-block kb+1 globals into registers ----
        if (kb1 < nblocks) {
            const int bk1 = kb1 * BKO;
#pragma unroll
            for (int i = 0; i < 2; i++) {
                const int lin = t + i * 256;
                pa[i] = *(const float4*)(Ag + (size_t)(lin >> 2) * lda + bk1 + (lin & 3) * 4);
                pb[i] = *(const float4*)(Bg + (size_t)(bk1 + (lin >> 5)) * ldb + (lin & 31) * 4);
            }
        }

        // ---- compute: 3 MMA groups on staged tiles (k = 16) ----
        {
            uint32_t ah[2][4], al[2][4];
#pragma unroll
            for (int mt = 0; mt < 2; mt++) {
                const int aoff = (wm * 32 + mt * 16 + mrow) * LDSA2 + mcol;
                ldsm_x4(ah[mt], (uint32_t)__cvta_generic_to_shared(&Ah[cur][aoff]));
                ldsm_x4(al[mt], (uint32_t)__cvta_generic_to_shared(&Al[cur][aoff]));
            }
#pragma unroll
            for (int ntp = 0; ntp < 4; ntp++) {
                uint32_t bh[4], bl[4];
                const int boff = mrow * LDSB2 + wn * 64 + ntp * 16 + mcol;
                ldsm_x4_t(bh, (uint32_t)__cvta_generic_to_shared(&Bh[cur][boff]));
                ldsm_x4_t(bl, (uint32_t)__cvta_generic_to_shared(&Bl[cur][boff]));
#pragma unroll
                for (int mt = 0; mt < 2; mt++) {
                    mma16816(acc[mt][ntp * 2 + 0], ah[mt], bh[0], bh[1]);
                    mma16816(acc[mt][ntp * 2 + 0], al[mt], bh[0], bh[1]);
                    mma16816(acc[mt][ntp * 2 + 0], ah[mt], bl[0], bl[1]);
                    mma16816(acc[mt][ntp * 2 + 1], ah[mt], bh[2], bh[3]);
                    mma16816(acc[mt][ntp * 2 + 1], al[mt], bh[2], bh[3]);
                    mma16816(acc[mt][ntp * 2 + 1], ah[mt], bl[2], bl[3]);
                }
            }
        }

        // ---- convert + stage k-block kb+1 into buf `nxt`, ONE barrier ----
        if (kb1 < nblocks) {
#pragma unroll
            for (int i = 0; i < 2; i++) {
                const int lin = t + i * 256;
                uint2 vah, val, vbh, vbl;
                pack_hilo(pa[i].x, pa[i].y, vah.x, val.x);
                pack_hilo(pa[i].z, pa[i].w, vah.y, val.y);
                pack_hilo(pb[i].x, pb[i].y, vbh.x, vbl.x);
                pack_hilo(pb[i].z, pb[i].w, vbh.y, vbl.y);
                const int aoff = (lin >> 2) * LDSA2 + (lin & 3) * 4;
                const int boff = (lin >> 5) * LDSB2 + (lin & 31) * 4;
                *(uint2*)&Ah[nxt][aoff] = vah;  *(uint2*)&Al[nxt][aoff] = val;
                *(uint2*)&Bh[nxt][boff] = vbh;  *(uint2*)&Bl[nxt][boff] = vbl;
            }
            __syncthreads();   // k-block kb+1 visible; also fences buf reuse
        }
    }

    // ---- epilogue: + bias, float2 stores ----
    const int row_base = blockIdx.y * GBM + wm * 32 + g;
    const int col_base = blockIdx.x * GBN + wn * 64 + tg * 2;
#pragma unroll
    for (int nt = 0; nt < 8; nt++) {
        const int col = col_base + nt * 8;
        const float b0 = bias[col], b1 = bias[col + 1];
#pragma unroll
        for (int mt = 0; mt < 2; mt++) {
            const int r = row_base + mt * 16;
            float2 v0 = make_float2(acc[mt][nt][0] + b0, acc[mt][nt][1] + b1);
            float2 v1 = make_float2(acc[mt][nt][2] + b0, acc[mt][nt][3] + b1);
            *(float2*)(Cz + (size_t)r * ldc + col)       = v0;
            *(float2*)(Cz + (size_t)(r + 8) * ldc + col) = v1;
        }
    }
}

// ---------------------------------------------------------------------------
// Per-token head-vs-head attention (fp32 path).
// One CTA per token (256 threads, 8 warps); warp w owns head w.
// ---------------------------------------------------------------------------
__global__ void __launch_bounds__(256)
attn_kernel(const float* __restrict__ qkv, float* __restrict__ o1)
{
    __shared__ float s[3 * HD];
    const size_t tok = blockIdx.x;

    const float4* src = (const float4*)(qkv + tok * (size_t)(3 * HD));
    float4* dst = (float4*)s;
#pragma unroll
    for (int i = threadIdx.x; i < (3 * HD) / 4; i += 256) dst[i] = src[i];
    __syncthreads();

    const float* sq = s;
    const float* sk = s + HD;
    const float* sv = s + 2 * HD;

    const int w    = threadIdx.x >> 5;
    const int lane = threadIdx.x & 31;
    const float scale = 0.0625f;   // 1/sqrt(256)

    float a[H];
#pragma unroll
    for (int gg = 0; gg < H; gg++) {
        float sum = 0.0f;
#pragma unroll
        for (int m = 0; m < 8; m++) {
            const int dd = lane + 32 * m;
            sum += sq[w * D + dd] * sk[gg * D + dd];
        }
#pragma unroll
        for (int off = 16; off; off >>= 1)
            sum += __shfl_xor_sync(0xffffffffu, sum, off);
        a[gg] = sum * scale;
    }

    float mx = a[0];
#pragma unroll
    for (int gg = 1; gg < H; gg++) mx = fmaxf(mx, a[gg]);
    float ssum = 0.0f;
#pragma unroll
    for (int gg = 0; gg < H; gg++) { a[gg] = expf(a[gg] - mx); ssum += a[gg]; }
    const float inv = 1.0f / ssum;
#pragma unroll
    for (int gg = 0; gg < H; gg++) a[gg] *= inv;

    float* orow = o1 + tok * (size_t)HD + w * D;
#pragma unroll
    for (int m = 0; m < 8; m++) {
        const int dd = lane + 32 * m;
        float o = 0.0f;
#pragma unroll
        for (int gg = 0; gg < H; gg++) o += a[gg] * sv[gg * D + dd];
        orow[dd] = o;
    }
}

// ---------------------------------------------------------------------------
extern "C" void kernel_launch(void* const* d_in, const int* in_sizes, int n_in,
                              void* d_out, int out_size)
{
    const float* x  = (const float*)d_in[0];
    const float* Wq = (const float*)d_in[1];
    const float* bq = (const float*)d_in[2];
    const float* Wk = (const float*)d_in[3];
    const float* bk = (const float*)d_in[4];
    const float* Wv = (const float*)d_in[5];
    const float* bv = (const float*)d_in[6];
    const float* Wo = (const float*)d_in[7];
    const float* bo = (const float*)d_in[8];
    float* out = (float*)d_out;

    const int M = in_sizes[0] / D;   // 16384 tokens

    float *qkv, *o1;
    cudaGetSymbolAddress((void**)&qkv, g_qkv);
    cudaGetSymbolAddress((void**)&o1,  g_o1);

    dim3 blk(256);

    // Fused QKV projections: X(M x 256) @ {Wq,Wk,Wv}(256 x 2048) + b
    dim3 gA(HD / GBN, M / GBM, 3);
    gemm_bf16x3<<<gA, blk>>>(x, Wq, bq, Wk, bk, Wv, bv,
                             qkv, HD, D, D, HD, 3 * HD);

    // Per-token attention
    attn_kernel<<<M, blk>>>(qkv, o1);

    // Output projection: O1(M x 2048) @ Wo(2048 x 256) + bo
    dim3 gC(D / GBN, M / GBM, 1);
    gemm_bf16x3<<<gC, blk>>>(o1, Wo, bo, Wo, bo, Wo, bo,
                             out, 0, HD, HD, D, D);
}